// round 7
// baseline (speedup 1.0000x reference)
#include <cuda_runtime.h>

// HashEncoding (instant-NGP multires hash grid), sm_103a.
// Governing law (R3-R6, 3x confirmed): dur ~= gather L1-lines * 0.93cyc / 148
// SMs, IF the gather set stays L2-resident. R5/R6 dense paths underperformed
// because 128MB of streaming output writes thrash L2 and evict the record
// tables -> DRAM latency at MLP=1.
// R7: (a) __stwt streaming stores for all outputs (don't allocate in L2);
// (b) levels 0-6: full 8-corner 64B record = 1 line per point-level (32.7MB);
//     levels 7-8: 32B y/z-quad = 2 lines (49.4MB); total 82MB < L2.
// Lines: 11M dense + 56M hash = 67M (R4 fused: 92M).

#define TABLE_SIZE (1u << 19)
#define HASH_MASK  (TABLE_SIZE - 1u)
#define P1 2654435761u
#define P2 805459861u
#define N_SMALL 9   // dense levels 0..8
#define N_REC64 7   // levels 0..6 use 64B records

// int(16 * 32**(i/15)) with host libm pow: level 9 = 127 (confirmed R1/R2).
__constant__ int d_res[16] = {16, 20, 25, 32, 40, 50, 64, 80,
                              101, 127, 161, 203, 256, 322, 406, 512};
// cumulative r^3 for levels 0..8 (corner temp offsets)
__constant__ int d_cstart[N_SMALL] = {0, 4096, 12096, 27721, 60489,
                                      124489, 249489, 511633, 1023633};
// 64B-record pool offsets, levels 0..6 (in record units)
__constant__ int d_rstart[N_REC64] = {0, 4096, 12096, 27721, 60489,
                                      124489, 249489};
#define REC64_TOTAL 511633
// 32B-quad pool offsets, levels 7..8 (in quad units)
__constant__ int d_qstart[2] = {0, 512000};
#define QUAD_TOTAL 1542301   // 80^3 + 101^3
#define CORNER_TOTAL 2053934

__device__ float2 g_corner[CORNER_TOTAL];              // 16.4 MB temp
__device__ float4 g_rec64[(size_t)REC64_TOTAL * 4];    // 32.7 MB
__device__ float4 g_quad[(size_t)QUAD_TOTAL * 2];      // 49.4 MB

// q = trunc(((c/res + 1) * 0.5) * 2^18); division via div.full.f32 to match
// XLA-GPU's fast-path lowering (bit-exact requirement, established R3).
__device__ __forceinline__ unsigned qval(int c, float resf) {
    float d;
    asm("div.full.f32 %0, %1, %2;" : "=f"(d) : "f"((float)c), "f"(resf));
    float v = __fmul_rn(__fadd_rn(d, 1.0f), 131072.0f);
    return (unsigned)v;
}

// Phase 1: one hashed gather per unique dense corner.
__global__ __launch_bounds__(256)
void pre_corners(const float2* __restrict__ tables) {
    int level = blockIdx.y;
    int r = d_res[level];
    int n = r * r * r;
    int i = blockIdx.x * blockDim.x + threadIdx.x;
    if (i >= n) return;
    int c = i % r;
    int t = i / r;
    int b = t % r;
    int a = t / r;
    float resf = (float)r;
    unsigned h = qval(a, resf) + qval(b, resf) * P1 + qval(c, resf) * P2;
    const float2* tab = tables + (size_t)level * TABLE_SIZE;
    g_corner[d_cstart[level] + i] = __ldg(&tab[h & HASH_MASK]);
}

// Phase 2a: levels 0-6, assemble 64B 8-corner records.
__global__ __launch_bounds__(256)
void pre_rec64() {
    int level = blockIdx.y;
    int r = d_res[level];
    int n = r * r * r;
    int i = blockIdx.x * blockDim.x + threadIdx.x;
    if (i >= n) return;
    int c = i % r;
    int t = i / r;
    int b = t % r;
    int a = t / r;
    int a1 = (a + 1 == r) ? 0 : a + 1;
    int b1 = (b + 1 == r) ? 0 : b + 1;
    int c1 = (c + 1 == r) ? 0 : c + 1;
    const float2* tc = g_corner + d_cstart[level];
    int r00 = (a * r + b) * r,  r01 = (a * r + b1) * r;
    int r10 = (a1 * r + b) * r, r11 = (a1 * r + b1) * r;
    float2 f000 = tc[r00 + c], f001 = tc[r00 + c1];
    float2 f010 = tc[r01 + c], f011 = tc[r01 + c1];
    float2 f100 = tc[r10 + c], f101 = tc[r10 + c1];
    float2 f110 = tc[r11 + c], f111 = tc[r11 + c1];
    float4* rec = g_rec64 + (size_t)(d_rstart[level] + i) * 4;
    rec[0] = make_float4(f000.x, f000.y, f001.x, f001.y);  // x0 y0
    rec[1] = make_float4(f010.x, f010.y, f011.x, f011.y);  // x0 y1
    rec[2] = make_float4(f100.x, f100.y, f101.x, f101.y);  // x1 y0
    rec[3] = make_float4(f110.x, f110.y, f111.x, f111.y);  // x1 y1
}

// Phase 2b: levels 7-8, assemble 32B y/z quads.
__global__ __launch_bounds__(256)
void pre_quad32() {
    int lv = blockIdx.y;           // 0,1 -> level 7,8
    int level = 7 + lv;
    int r = d_res[level];
    int n = r * r * r;
    int i = blockIdx.x * blockDim.x + threadIdx.x;
    if (i >= n) return;
    int c = i % r;
    int t = i / r;
    int b = t % r;
    int a = t / r;
    int b1 = (b + 1 == r) ? 0 : b + 1;
    int c1 = (c + 1 == r) ? 0 : c + 1;
    const float2* tc = g_corner + d_cstart[level];
    int r0 = (a * r + b) * r;
    int r1 = (a * r + b1) * r;
    float2 f00 = tc[r0 + c], f01 = tc[r0 + c1];
    float2 f10 = tc[r1 + c], f11 = tc[r1 + c1];
    float4* qd = g_quad + (size_t)(d_qstart[lv] + i) * 2;
    qd[0] = make_float4(f00.x, f00.y, f01.x, f01.y);  // y0: (z0,z1)
    qd[1] = make_float4(f10.x, f10.y, f11.x, f11.y);  // y1: (z0,z1)
}

// Dense levels 0-8: 4 lanes per (point,level). Lane q handles corner pair
// (x_{q>>1}, y_{q&1}, z0/z1) via one LDG.128, then 2 shfl-xor reductions.
__global__ __launch_bounds__(256)
void encode_dense(const float* __restrict__ x,
                  float2* __restrict__ out, int n_pts)
{
    int t = blockIdx.x * blockDim.x + threadIdx.x;
    int q = t & 3;
    int qid = t >> 2;
    bool valid = qid < n_pts * N_SMALL;
    int cqid = valid ? qid : 0;
    int point = cqid / N_SMALL;
    int level = cqid - point * N_SMALL;

    float px = fminf(fmaxf(__ldg(x + 3 * point + 0), -1.0f), 1.0f);
    float py = fminf(fmaxf(__ldg(x + 3 * point + 1), -1.0f), 1.0f);
    float pz = fminf(fmaxf(__ldg(x + 3 * point + 2), -1.0f), 1.0f);

    int r = d_res[level];
    float resf = (float)r;
    float cx = __fmul_rn(px, resf);
    float cy = __fmul_rn(py, resf);
    float cz = __fmul_rn(pz, resf);
    float fx = floorf(cx), fy = floorf(cy), fz = floorf(cz);
    float lx = __fsub_rn(cx, fx);
    float ly = __fsub_rn(cy, fy);
    float lz = __fsub_rn(cz, fz);
    int ix = (int)fx, iy = (int)fy, iz = (int)fz;
    int x0 = ix;     if (x0 < 0) x0 += r; else if (x0 >= r) x0 -= r;
    int x1 = ix + 1; if (x1 < 0) x1 += r; else if (x1 >= r) x1 -= r;
    int y0 = iy;     if (y0 < 0) y0 += r; else if (y0 >= r) y0 -= r;
    int z0 = iz;     if (z0 < 0) z0 += r; else if (z0 >= r) z0 -= r;

    const float4* src;
    if (level < N_REC64) {
        int cell = d_rstart[level] + (x0 * r + y0) * r + z0;
        src = g_rec64 + (size_t)cell * 4 + q;
    } else {
        int xs = (q >> 1) ? x1 : x0;
        int cell = d_qstart[level - N_REC64] + (xs * r + y0) * r + z0;
        src = g_quad + (size_t)cell * 2 + (q & 1);
    }
    float4 v = __ldg(src);

    float wq = ((q >> 1) ? lx : 1.0f - lx) * ((q & 1) ? ly : 1.0f - ly);
    float wz0 = 1.0f - lz;
    float pax = wq * (wz0 * v.x + lz * v.z);
    float pay = wq * (wz0 * v.y + lz * v.w);
    pax += __shfl_xor_sync(0xFFFFFFFFu, pax, 1);
    pay += __shfl_xor_sync(0xFFFFFFFFu, pay, 1);
    pax += __shfl_xor_sync(0xFFFFFFFFu, pax, 2);
    pay += __shfl_xor_sync(0xFFFFFFFFu, pay, 2);
    if (q == 0 && valid)
        __stwt(&out[(size_t)point * 16 + level], make_float2(pax, pay));
}

// Hash levels 9-15: 8 scattered 8B gathers (at the wavefront floor, R5/R6).
__global__ __launch_bounds__(256)
void encode_hash(const float* __restrict__ x,
                 const float2* __restrict__ tables,
                 float2* __restrict__ out, int n_pts)
{
    int t = blockIdx.x * blockDim.x + threadIdx.x;
    if (t >= n_pts * 7) return;
    int point = t / 7;
    int level = 9 + (t - point * 7);

    float px = fminf(fmaxf(__ldg(x + 3 * point + 0), -1.0f), 1.0f);
    float py = fminf(fmaxf(__ldg(x + 3 * point + 1), -1.0f), 1.0f);
    float pz = fminf(fmaxf(__ldg(x + 3 * point + 2), -1.0f), 1.0f);

    int res = d_res[level];
    float resf = (float)res;
    float cx = __fmul_rn(px, resf);
    float cy = __fmul_rn(py, resf);
    float cz = __fmul_rn(pz, resf);
    float fx = floorf(cx), fy = floorf(cy), fz = floorf(cz);
    float lx = __fsub_rn(cx, fx);
    float ly = __fsub_rn(cy, fy);
    float lz = __fsub_rn(cz, fz);
    int ix = (int)fx, iy = (int)fy, iz = (int)fz;

    int x0 = ix;     if (x0 < 0) x0 += res; else if (x0 >= res) x0 -= res;
    int x1 = ix + 1; if (x1 < 0) x1 += res; else if (x1 >= res) x1 -= res;
    int y0 = iy;     if (y0 < 0) y0 += res; else if (y0 >= res) y0 -= res;
    int y1 = iy + 1; if (y1 < 0) y1 += res; else if (y1 >= res) y1 -= res;
    int z0 = iz;     if (z0 < 0) z0 += res; else if (z0 >= res) z0 -= res;
    int z1 = iz + 1; if (z1 < 0) z1 += res; else if (z1 >= res) z1 -= res;

    unsigned hx[2], hy[2], hz[2];
    hx[0] = qval(x0, resf);
    hx[1] = qval(x1, resf);
    hy[0] = qval(y0, resf) * P1;
    hy[1] = qval(y1, resf) * P1;
    hz[0] = qval(z0, resf) * P2;
    hz[1] = qval(z1, resf) * P2;

    const float2* tab = tables + (size_t)level * TABLE_SIZE;
    float2 f[8];
#pragma unroll
    for (int c = 0; c < 8; c++) {
        unsigned idx = (hx[(c >> 2) & 1] + hy[(c >> 1) & 1] + hz[c & 1]) & HASH_MASK;
        f[c] = __ldg(&tab[idx]);
    }
    float wxa[2] = {1.0f - lx, lx};
    float wya[2] = {1.0f - ly, ly};
    float wza[2] = {1.0f - lz, lz};
    float ax = 0.0f, ay = 0.0f;
#pragma unroll
    for (int c = 0; c < 8; c++) {
        float w = wxa[(c >> 2) & 1] * wya[(c >> 1) & 1] * wza[c & 1];
        ax += w * f[c].x;
        ay += w * f[c].y;
    }
    __stwt(&out[(size_t)point * 16 + level], make_float2(ax, ay));
}

extern "C" void kernel_launch(void* const* d_in, const int* in_sizes, int n_in,
                              void* d_out, int out_size) {
    const float* x = (const float*)d_in[0];
    const float2* tables = (const float2*)d_in[1];
    float2* out = (float2*)d_out;
    int n_pts = in_sizes[0] / 3;

    dim3 gc((1030301 + 255) / 256, N_SMALL);   // corners: all 9 levels
    pre_corners<<<gc, 256>>>(tables);
    dim3 gr((262144 + 255) / 256, N_REC64);    // rec64: max r^3 = 64^3
    pre_rec64<<<gr, 256>>>();
    dim3 gq((1030301 + 255) / 256, 2);         // quads: levels 7,8
    pre_quad32<<<gq, 256>>>();

    long long nd = (long long)n_pts * N_SMALL * 4;
    encode_dense<<<(int)((nd + 255) / 256), 256>>>(x, out, n_pts);

    long long nh = (long long)n_pts * 7;
    encode_hash<<<(int)((nh + 255) / 256), 256>>>(x, tables, out, n_pts);
}

// round 8
// speedup vs baseline: 1.2634x; 1.2634x over previous
#include <cuda_runtime.h>

// HashEncoding (instant-NGP multires hash grid), sm_103a.
// R7 measurements: encode_hash 194us (L1=92%, issue=21%, memory-bound floor);
// encode_dense 215us (L1=37%, issue=58%, ALU-bound from 4x replicated setup).
// R8: fuse them with intra-block warp specialization -- 10 warps dense-coop
// (80 point-levels) + 2 warps hash (64 point-levels) per 384-thread block.
// Each SM overlaps dense issue pressure with hash memory latency; fused time
// ~= max(L1-line work ~235us, issue work ~166us) instead of the 409us sum.

#define TABLE_SIZE (1u << 19)
#define HASH_MASK  (TABLE_SIZE - 1u)
#define P1 2654435761u
#define P2 805459861u
#define N_SMALL 9   // dense levels 0..8
#define N_REC64 7   // levels 0..6 use 64B records

// int(16 * 32**(i/15)) with host libm pow: level 9 = 127 (confirmed R1/R2).
__constant__ int d_res[16] = {16, 20, 25, 32, 40, 50, 64, 80,
                              101, 127, 161, 203, 256, 322, 406, 512};
__constant__ int d_cstart[N_SMALL] = {0, 4096, 12096, 27721, 60489,
                                      124489, 249489, 511633, 1023633};
__constant__ int d_rstart[N_REC64] = {0, 4096, 12096, 27721, 60489,
                                      124489, 249489};
#define REC64_TOTAL 511633
__constant__ int d_qstart[2] = {0, 512000};
#define QUAD_TOTAL 1542301   // 80^3 + 101^3
#define CORNER_TOTAL 2053934

__device__ float2 g_corner[CORNER_TOTAL];              // 16.4 MB temp
__device__ float4 g_rec64[(size_t)REC64_TOTAL * 4];    // 32.7 MB
__device__ float4 g_quad[(size_t)QUAD_TOTAL * 2];      // 49.4 MB

// q = trunc(((c/res + 1) * 0.5) * 2^18); division via div.full.f32 to match
// XLA-GPU's fast-path lowering (bit-exact requirement, established R3).
__device__ __forceinline__ unsigned qval(int c, float resf) {
    float d;
    asm("div.full.f32 %0, %1, %2;" : "=f"(d) : "f"((float)c), "f"(resf));
    float v = __fmul_rn(__fadd_rn(d, 1.0f), 131072.0f);
    return (unsigned)v;
}

__global__ __launch_bounds__(256)
void pre_corners(const float2* __restrict__ tables) {
    int level = blockIdx.y;
    int r = d_res[level];
    int n = r * r * r;
    int i = blockIdx.x * blockDim.x + threadIdx.x;
    if (i >= n) return;
    int c = i % r;
    int t = i / r;
    int b = t % r;
    int a = t / r;
    float resf = (float)r;
    unsigned h = qval(a, resf) + qval(b, resf) * P1 + qval(c, resf) * P2;
    const float2* tab = tables + (size_t)level * TABLE_SIZE;
    g_corner[d_cstart[level] + i] = __ldg(&tab[h & HASH_MASK]);
}

__global__ __launch_bounds__(256)
void pre_rec64() {
    int level = blockIdx.y;
    int r = d_res[level];
    int n = r * r * r;
    int i = blockIdx.x * blockDim.x + threadIdx.x;
    if (i >= n) return;
    int c = i % r;
    int t = i / r;
    int b = t % r;
    int a = t / r;
    int a1 = (a + 1 == r) ? 0 : a + 1;
    int b1 = (b + 1 == r) ? 0 : b + 1;
    int c1 = (c + 1 == r) ? 0 : c + 1;
    const float2* tc = g_corner + d_cstart[level];
    int r00 = (a * r + b) * r,  r01 = (a * r + b1) * r;
    int r10 = (a1 * r + b) * r, r11 = (a1 * r + b1) * r;
    float2 f000 = tc[r00 + c], f001 = tc[r00 + c1];
    float2 f010 = tc[r01 + c], f011 = tc[r01 + c1];
    float2 f100 = tc[r10 + c], f101 = tc[r10 + c1];
    float2 f110 = tc[r11 + c], f111 = tc[r11 + c1];
    float4* rec = g_rec64 + (size_t)(d_rstart[level] + i) * 4;
    rec[0] = make_float4(f000.x, f000.y, f001.x, f001.y);
    rec[1] = make_float4(f010.x, f010.y, f011.x, f011.y);
    rec[2] = make_float4(f100.x, f100.y, f101.x, f101.y);
    rec[3] = make_float4(f110.x, f110.y, f111.x, f111.y);
}

__global__ __launch_bounds__(256)
void pre_quad32() {
    int lv = blockIdx.y;           // 0,1 -> level 7,8
    int level = 7 + lv;
    int r = d_res[level];
    int n = r * r * r;
    int i = blockIdx.x * blockDim.x + threadIdx.x;
    if (i >= n) return;
    int c = i % r;
    int t = i / r;
    int b = t % r;
    int a = t / r;
    int b1 = (b + 1 == r) ? 0 : b + 1;
    int c1 = (c + 1 == r) ? 0 : c + 1;
    const float2* tc = g_corner + d_cstart[level];
    int r0 = (a * r + b) * r;
    int r1 = (a * r + b1) * r;
    float2 f00 = tc[r0 + c], f01 = tc[r0 + c1];
    float2 f10 = tc[r1 + c], f11 = tc[r1 + c1];
    float4* qd = g_quad + (size_t)(d_qstart[lv] + i) * 2;
    qd[0] = make_float4(f00.x, f00.y, f01.x, f01.y);
    qd[1] = make_float4(f10.x, f10.y, f11.x, f11.y);
}

// Fused encoder: warps 0-9 dense (4 lanes per point-level, 1 line each),
// warps 10-11 hash (1 thread per point-level, 8 lines each).
__global__ __launch_bounds__(384)
void encode_fused(const float* __restrict__ x,
                  const float2* __restrict__ tables,
                  float2* __restrict__ out, int n_pts)
{
    int wid = threadIdx.x >> 5;
    int lane = threadIdx.x & 31;

    if (wid < 10) {
        // ---- dense path: levels 0..8 ----
        int q = lane & 3;
        long long qid = ((long long)blockIdx.x * 10 + wid) * 8 + (lane >> 2);
        bool valid = qid < (long long)n_pts * N_SMALL;
        long long cqid = valid ? qid : 0;
        int point = (int)(cqid / N_SMALL);
        int level = (int)(cqid - (long long)point * N_SMALL);

        float px = fminf(fmaxf(__ldg(x + 3 * point + 0), -1.0f), 1.0f);
        float py = fminf(fmaxf(__ldg(x + 3 * point + 1), -1.0f), 1.0f);
        float pz = fminf(fmaxf(__ldg(x + 3 * point + 2), -1.0f), 1.0f);

        int r = d_res[level];
        float resf = (float)r;
        float cx = __fmul_rn(px, resf);
        float cy = __fmul_rn(py, resf);
        float cz = __fmul_rn(pz, resf);
        float fx = floorf(cx), fy = floorf(cy), fz = floorf(cz);
        float lx = __fsub_rn(cx, fx);
        float ly = __fsub_rn(cy, fy);
        float lz = __fsub_rn(cz, fz);
        int ix = (int)fx, iy = (int)fy, iz = (int)fz;
        int x0 = ix;     if (x0 < 0) x0 += r; else if (x0 >= r) x0 -= r;
        int x1 = ix + 1; if (x1 < 0) x1 += r; else if (x1 >= r) x1 -= r;
        int y0 = iy;     if (y0 < 0) y0 += r; else if (y0 >= r) y0 -= r;
        int z0 = iz;     if (z0 < 0) z0 += r; else if (z0 >= r) z0 -= r;

        const float4* src;
        if (level < N_REC64) {
            int cell = d_rstart[level] + (x0 * r + y0) * r + z0;
            src = g_rec64 + (size_t)cell * 4 + q;
        } else {
            int xs = (q >> 1) ? x1 : x0;
            int cell = d_qstart[level - N_REC64] + (xs * r + y0) * r + z0;
            src = g_quad + (size_t)cell * 2 + (q & 1);
        }
        float4 v = __ldg(src);

        float wq = ((q >> 1) ? lx : 1.0f - lx) * ((q & 1) ? ly : 1.0f - ly);
        float wz0 = 1.0f - lz;
        float pax = wq * (wz0 * v.x + lz * v.z);
        float pay = wq * (wz0 * v.y + lz * v.w);
        pax += __shfl_xor_sync(0xFFFFFFFFu, pax, 1);
        pay += __shfl_xor_sync(0xFFFFFFFFu, pay, 1);
        pax += __shfl_xor_sync(0xFFFFFFFFu, pax, 2);
        pay += __shfl_xor_sync(0xFFFFFFFFu, pay, 2);
        if (q == 0 && valid)
            __stwt(&out[(size_t)point * 16 + level], make_float2(pax, pay));
    } else {
        // ---- hash path: levels 9..15 ----
        long long t = ((long long)blockIdx.x * 2 + (wid - 10)) * 32 + lane;
        if (t >= (long long)n_pts * 7) return;
        int point = (int)(t / 7);
        int level = 9 + (int)(t - (long long)point * 7);

        float px = fminf(fmaxf(__ldg(x + 3 * point + 0), -1.0f), 1.0f);
        float py = fminf(fmaxf(__ldg(x + 3 * point + 1), -1.0f), 1.0f);
        float pz = fminf(fmaxf(__ldg(x + 3 * point + 2), -1.0f), 1.0f);

        int res = d_res[level];
        float resf = (float)res;
        float cx = __fmul_rn(px, resf);
        float cy = __fmul_rn(py, resf);
        float cz = __fmul_rn(pz, resf);
        float fx = floorf(cx), fy = floorf(cy), fz = floorf(cz);
        float lx = __fsub_rn(cx, fx);
        float ly = __fsub_rn(cy, fy);
        float lz = __fsub_rn(cz, fz);
        int ix = (int)fx, iy = (int)fy, iz = (int)fz;

        int x0 = ix;     if (x0 < 0) x0 += res; else if (x0 >= res) x0 -= res;
        int x1 = ix + 1; if (x1 < 0) x1 += res; else if (x1 >= res) x1 -= res;
        int y0 = iy;     if (y0 < 0) y0 += res; else if (y0 >= res) y0 -= res;
        int y1 = iy + 1; if (y1 < 0) y1 += res; else if (y1 >= res) y1 -= res;
        int z0 = iz;     if (z0 < 0) z0 += res; else if (z0 >= res) z0 -= res;
        int z1 = iz + 1; if (z1 < 0) z1 += res; else if (z1 >= res) z1 -= res;

        unsigned hx[2], hy[2], hz[2];
        hx[0] = qval(x0, resf);
        hx[1] = qval(x1, resf);
        hy[0] = qval(y0, resf) * P1;
        hy[1] = qval(y1, resf) * P1;
        hz[0] = qval(z0, resf) * P2;
        hz[1] = qval(z1, resf) * P2;

        const float2* tab = tables + (size_t)level * TABLE_SIZE;
        float2 f[8];
#pragma unroll
        for (int c = 0; c < 8; c++) {
            unsigned idx = (hx[(c >> 2) & 1] + hy[(c >> 1) & 1] + hz[c & 1]) & HASH_MASK;
            f[c] = __ldg(&tab[idx]);
        }
        float wxa[2] = {1.0f - lx, lx};
        float wya[2] = {1.0f - ly, ly};
        float wza[2] = {1.0f - lz, lz};
        float ax = 0.0f, ay = 0.0f;
#pragma unroll
        for (int c = 0; c < 8; c++) {
            float w = wxa[(c >> 2) & 1] * wya[(c >> 1) & 1] * wza[c & 1];
            ax += w * f[c].x;
            ay += w * f[c].y;
        }
        __stwt(&out[(size_t)point * 16 + level], make_float2(ax, ay));
    }
}

extern "C" void kernel_launch(void* const* d_in, const int* in_sizes, int n_in,
                              void* d_out, int out_size) {
    const float* x = (const float*)d_in[0];
    const float2* tables = (const float2*)d_in[1];
    float2* out = (float2*)d_out;
    int n_pts = in_sizes[0] / 3;

    dim3 gc((1030301 + 255) / 256, N_SMALL);
    pre_corners<<<gc, 256>>>(tables);
    dim3 gr((262144 + 255) / 256, N_REC64);
    pre_rec64<<<gr, 256>>>();
    dim3 gq((1030301 + 255) / 256, 2);
    pre_quad32<<<gq, 256>>>();

    // fused: 80 dense pl + 64 hash pl per block; dense determines block count
    long long dense_pl = (long long)n_pts * N_SMALL;
    int blocks = (int)((dense_pl + 79) / 80);
    // hash coverage check: blocks*64 >= n_pts*7 holds for n_pts*9/80 blocks
    encode_fused<<<blocks, 384>>>(x, tables, out, n_pts);
}